// round 1
// baseline (speedup 1.0000x reference)
#include <cuda_runtime.h>

#define KSEL 8
#define NB   16384
#define BQ   65536
#define FDIM 64
#define EPSF 1e-8f
#define INV_TEMP 200.0f   // 1 / (2*0.05*0.05)

#define TILE 2048
#define TPB  256

// Packed anchors: {px, py, pz, inv_w2}
__device__ float4 g_pack[NB];

__global__ void prep_kernel(const float* __restrict__ pos,
                            const float* __restrict__ w) {
    int i = blockIdx.x * blockDim.x + threadIdx.x;
    if (i < NB) {
        float wi = w[i];
        float a = 1.0f / (wi * wi + EPSF);
        g_pack[i] = make_float4(pos[3 * i + 0], pos[3 * i + 1], pos[3 * i + 2], a);
    }
}

__global__ __launch_bounds__(TPB) void knn_kernel(
    const float* __restrict__ coords,
    const float* __restrict__ features,
    float* __restrict__ out)
{
    // Anchor tile and epilogue handoff share the same shared memory.
    __shared__ union SMem {
        float4 anch[TILE];                      // 32 KB
        struct {
            int   idx[TPB][KSEL];               // 8 KB
            float w[TPB][KSEL];                 // 8 KB
        } ep;
    } sm;

    const int q = blockIdx.x * TPB + threadIdx.x;
    const float cx = coords[3 * q + 0];
    const float cy = coords[3 * q + 1];
    const float cz = coords[3 * q + 2];

    float d[KSEL];
    int   id[KSEL];
#pragma unroll
    for (int k = 0; k < KSEL; ++k) { d[k] = 3.4e38f; id[k] = 0; }

    for (int t0 = 0; t0 < NB; t0 += TILE) {
        __syncthreads();
#pragma unroll
        for (int j = threadIdx.x; j < TILE; j += TPB)
            sm.anch[j] = g_pack[t0 + j];
        __syncthreads();

        float worst = d[KSEL - 1];
#pragma unroll 4
        for (int j = 0; j < TILE; ++j) {
            float4 p = sm.anch[j];
            float dx = cx - p.x;
            float dy = cy - p.y;
            float dz = cz - p.z;
            float sq = fmaf(dz, dz, fmaf(dy, dy, dx * dx)) * p.w;
            if (sq < worst) {
                d[KSEL - 1]  = sq;
                id[KSEL - 1] = t0 + j;
#pragma unroll
                for (int k = KSEL - 1; k > 0; --k) {
                    if (d[k] < d[k - 1]) {
                        float td = d[k]; d[k] = d[k - 1]; d[k - 1] = td;
                        int   ti = id[k]; id[k] = id[k - 1]; id[k - 1] = ti;
                    }
                }
                worst = d[KSEL - 1];
            }
        }
    }

    // Softmax over the 8 selected (logit = -sq * INV_TEMP), max-subtracted.
    float m = d[0];
    float wk[KSEL];
    float wsum = 0.0f;
#pragma unroll
    for (int k = 0; k < KSEL; ++k) {
        wk[k] = __expf((m - d[k]) * INV_TEMP);
        wsum += wk[k];
    }
    float inv = 1.0f / wsum;

    __syncthreads();   // everyone done reading sm.anch before overwrite
#pragma unroll
    for (int k = 0; k < KSEL; ++k) {
        sm.ep.w[threadIdx.x][k]   = wk[k] * inv;
        sm.ep.idx[threadIdx.x][k] = id[k];
    }
    __syncthreads();

    // Cooperative gather: each warp produces the 64-float output rows of its
    // 32 queries; lane L accumulates features [2L, 2L+1] (float2, coalesced).
    const int lane = threadIdx.x & 31;
    const int warp = threadIdx.x >> 5;
    for (int qq = 0; qq < 32; ++qq) {
        const int tq = warp * 32 + qq;
        float2 acc = make_float2(0.0f, 0.0f);
#pragma unroll
        for (int k = 0; k < KSEL; ++k) {
            const int   ii = sm.ep.idx[tq][k];
            const float ww = sm.ep.w[tq][k];
            float2 f = ((const float2*)(features + (size_t)ii * FDIM))[lane];
            acc.x = fmaf(ww, f.x, acc.x);
            acc.y = fmaf(ww, f.y, acc.y);
        }
        const int gq = blockIdx.x * TPB + tq;
        ((float2*)out)[gq * 32 + lane] = acc;
    }
}

extern "C" void kernel_launch(void* const* d_in, const int* in_sizes, int n_in,
                              void* d_out, int out_size) {
    const float* coords    = (const float*)d_in[0];
    const float* positions = (const float*)d_in[1];
    const float* weights   = (const float*)d_in[2];
    const float* features  = (const float*)d_in[3];
    float* out = (float*)d_out;

    prep_kernel<<<NB / 256, 256>>>(positions, weights);
    knn_kernel<<<BQ / TPB, TPB>>>(coords, features, out);
}